// round 16
// baseline (speedup 1.0000x reference)
#include <cuda_runtime.h>
#include <cuda_fp16.h>
#include <math_constants.h>
#include <cstdint>

#define NB   4
#define CIN  256
#define CI   128
#define HW   4096

// ---------------- helpers ----------------
__device__ __forceinline__ uint32_t smem_u32(const void* p) {
    uint32_t a;
    asm("{ .reg .u64 t; cvta.to.shared.u64 t, %1; cvt.u32.u64 %0, t; }" : "=r"(a) : "l"(p));
    return a;
}
__device__ __forceinline__ void ldsm4(uint32_t* r, uint32_t addr) {
    asm volatile("ldmatrix.sync.aligned.m8n8.x4.shared.b16 {%0,%1,%2,%3}, [%4];"
        : "=r"(r[0]), "=r"(r[1]), "=r"(r[2]), "=r"(r[3]) : "r"(addr));
}
__device__ __forceinline__ void mma_f16(float* c, const uint32_t* a, const uint32_t* b) {
    asm volatile("mma.sync.aligned.m16n8k16.row.col.f32.f16.f16.f32 "
        "{%0,%1,%2,%3}, {%4,%5,%6,%7}, {%8,%9}, {%0,%1,%2,%3};"
        : "+f"(c[0]), "+f"(c[1]), "+f"(c[2]), "+f"(c[3])
        : "r"(a[0]), "r"(a[1]), "r"(a[2]), "r"(a[3]), "r"(b[0]), "r"(b[1]));
}
__device__ __forceinline__ unsigned short f2h(float v) {
    return __half_as_ushort(__float2half_rn(v));
}
__device__ __forceinline__ float h2f(unsigned short u) {
    return __half2float(__ushort_as_half(u));
}
__device__ __forceinline__ uint32_t hmul2u(uint32_t a, uint32_t b) {
    __half2 r = __hmul2(*(__half2*)&a, *(__half2*)&b);
    return *(uint32_t*)&r;
}
__device__ __forceinline__ void cp16(uint32_t dst, const void* src) {
    asm volatile("cp.async.cg.shared.global [%0], [%1], 16;" :: "r"(dst), "l"(src));
}
#define CP_COMMIT() asm volatile("cp.async.commit_group;" ::: "memory")
#define CP_WAIT1()  asm volatile("cp.async.wait_group 1;" ::: "memory")
#define CP_WAIT0()  asm volatile("cp.async.wait_group 0;" ::: "memory")

// ---------------- scratch ----------------
__device__ __align__(16) unsigned short d_th[NB * HW * CI];  // theta^T hi [n][p][c]
__device__ __align__(16) unsigned short d_tl[NB * HW * CI];
__device__ __align__(16) unsigned short d_fh[NB * HW * CI];  // phi^T hi
__device__ __align__(16) unsigned short d_fl[NB * HW * CI];
__device__ __align__(16) unsigned short d_gh[NB * CI * HW];  // g hi [n][c][p]
__device__ __align__(16) unsigned short d_E [(size_t)NB * HW * HW]; // exp(S^T-pm) fp16 [n][j][i]
__device__ __align__(16) unsigned short d_wh[CIN * CI];      // w_w hi [co][c]
__device__ __align__(16) unsigned short d_wl[CIN * CI];      // w_w lo
__device__ float d_pm [NB * 32 * HW];
__device__ float d_pz [NB * 32 * HW];
__device__ float d_m  [NB * HW];
__device__ float d_rz [NB * HW];

// ============================================================================
// K0: w_w -> fp16 hi/lo
// ============================================================================
__global__ __launch_bounds__(256)
void w_prep(const float* __restrict__ ww)
{
    int i = (blockIdx.x * 256 + threadIdx.x) * 4;
    float4 v = *(const float4*)(ww + i);
    ushort4 h, l;
    h.x = f2h(v.x); h.y = f2h(v.y); h.z = f2h(v.z); h.w = f2h(v.w);
    l.x = f2h(v.x - h2f(h.x)); l.y = f2h(v.y - h2f(h.y));
    l.z = f2h(v.z - h2f(h.z)); l.w = f2h(v.w - h2f(h.w));
    *(ushort4*)(d_wh + i) = h;
    *(ushort4*)(d_wl + i) = l;
}

// ============================================================================
// K1: projections (fp32 SIMT) -> fp16 hi/lo; theta/phi transposed, g natural
// ============================================================================
__global__ __launch_bounds__(256)
void proj_kernel(const float* __restrict__ x,
                 const float* __restrict__ tw, const float* __restrict__ tb,
                 const float* __restrict__ pw, const float* __restrict__ pb,
                 const float* __restrict__ gw, const float* __restrict__ gb)
{
    const int jt = blockIdx.x, n = blockIdx.y, pr = blockIdx.z;
    const float *W, *B;
    if (pr == 0)      { W = tw; B = tb; }
    else if (pr == 1) { W = pw; B = pb; }
    else              { W = gw; B = gb; }
    const float* X = x + (size_t)n * CIN * HW + jt * 128;

    __shared__ float As[32][128];
    __shared__ float Bs[32][128];
    const int tid = threadIdx.x, tx = tid % 16, ty = tid / 16;

    float acc[8][8];
    #pragma unroll
    for (int i = 0; i < 8; i++)
        #pragma unroll
        for (int j = 0; j < 8; j++) acc[i][j] = 0.f;

    for (int k0 = 0; k0 < CIN; k0 += 32) {
        #pragma unroll
        for (int l = 0; l < 4; l++) {
            int idx = tid + l * 256, row = idx >> 3, kq = idx & 7;
            float4 v = *(const float4*)(W + row * CIN + k0 + kq * 4);
            As[kq*4+0][row] = v.x; As[kq*4+1][row] = v.y;
            As[kq*4+2][row] = v.z; As[kq*4+3][row] = v.w;
        }
        #pragma unroll
        for (int l = 0; l < 4; l++) {
            int idx = tid + l * 256, kk = idx >> 5, pq = idx & 31;
            *(float4*)&Bs[kk][pq*4] = *(const float4*)(X + (size_t)(k0+kk) * HW + pq * 4);
        }
        __syncthreads();
        #pragma unroll
        for (int kk = 0; kk < 32; kk++) {
            float a[8], b[8];
            *(float4*)(a)   = *(float4*)&As[kk][ty*4];
            *(float4*)(a+4) = *(float4*)&As[kk][64 + ty*4];
            *(float4*)(b)   = *(float4*)&Bs[kk][tx*4];
            *(float4*)(b+4) = *(float4*)&Bs[kk][64 + tx*4];
            #pragma unroll
            for (int i = 0; i < 8; i++)
                #pragma unroll
                for (int j = 0; j < 8; j++) acc[i][j] += a[i] * b[j];
        }
        __syncthreads();
    }
    #pragma unroll
    for (int r = 0; r < 8; r++) {
        int k = (r < 4) ? (ty*4 + r) : (64 + ty*4 + r - 4);
        float bias = B[k];
        #pragma unroll
        for (int c = 0; c < 8; c++) acc[r][c] += bias;
    }

    if (pr < 2) {
        unsigned short* Hh = (pr == 0) ? d_th : d_fh;
        unsigned short* Ll = (pr == 0) ? d_tl : d_fl;
        #pragma unroll
        for (int c = 0; c < 8; c++) {
            int p = (c < 4) ? (tx*4 + c) : (64 + tx*4 + c - 4);
            size_t ro = ((size_t)(n * HW + jt * 128 + p)) * 128;
            #pragma unroll
            for (int kh = 0; kh < 2; kh++) {
                int kb = kh ? (64 + ty*4) : (ty*4);
                ushort4 H, L;
                float v0 = acc[kh*4+0][c], v1 = acc[kh*4+1][c];
                float v2 = acc[kh*4+2][c], v3 = acc[kh*4+3][c];
                H.x = f2h(v0); H.y = f2h(v1); H.z = f2h(v2); H.w = f2h(v3);
                L.x = f2h(v0 - h2f(H.x)); L.y = f2h(v1 - h2f(H.y));
                L.z = f2h(v2 - h2f(H.z)); L.w = f2h(v3 - h2f(H.w));
                *(ushort4*)(Hh + ro + kb) = H;
                *(ushort4*)(Ll + ro + kb) = L;
            }
        }
    } else {
        #pragma unroll
        for (int r = 0; r < 8; r++) {
            int k = (r < 4) ? (ty*4 + r) : (64 + ty*4 + r - 4);
            size_t ro = ((size_t)(n * CI + k)) * HW + jt * 128;
            #pragma unroll
            for (int ph = 0; ph < 2; ph++) {
                int pb2 = ph ? (64 + tx*4) : (tx*4);
                ushort4 H;
                H.x = f2h(acc[r][ph*4+0]); H.y = f2h(acc[r][ph*4+1]);
                H.z = f2h(acc[r][ph*4+2]); H.w = f2h(acc[r][ph*4+3]);
                *(ushort4*)(d_gh + ro + pb2) = H;
            }
        }
    }
}

// ============================================================================
// K2: S^T[j][i] via mma.sync fp16 split (256 thr, 2 blocks/SM, cp.async).
// REGISTER-DIRECT epilogue: shuffle col-max, exp from regs, scattered E store,
// z partials in the same loop. No fp32 smem bounce buffer.
// grid = (it 32, jt 32, n 4)
// ============================================================================
#define SLDA 72
#define STILE 18432
#define S_DYN (4 * STILE)

__global__ __launch_bounds__(256, 2)
void s_gemm()
{
    extern __shared__ char sm[];
    const int it = blockIdx.x, jt = blockIdx.y, n = blockIdx.z;
    const int tid = threadIdx.x, wid = tid >> 5, lane = tid & 31;
    const int wm = wid & 3, wn = wid >> 2;
    const uint32_t sb = smem_u32(sm);
    const uint32_t AH = 0, AL = STILE, BH = 2*STILE, BL = 3*STILE;

    __shared__ float s_wm[4][128], s_mf[128];

    float acc[2][8][4];
    #pragma unroll
    for (int a = 0; a < 2; a++)
        #pragma unroll
        for (int b = 0; b < 8; b++)
            #pragma unroll
            for (int c = 0; c < 4; c++) acc[a][b][c] = 0.f;

    const int g = lane >> 3, lr = lane & 7;

    for (int kc = 0; kc < 2; kc++) {
        #pragma unroll
        for (int l = 0; l < 4; l++) {
            int u = tid + l * 256, r = u >> 3, k8 = u & 7;
            uint32_t doff = (uint32_t)(r * SLDA + k8 * 8) * 2;
            size_t ao = ((size_t)(n * HW + jt * 128 + r)) * 128 + kc * 64 + k8 * 8;
            size_t bo = ((size_t)(n * HW + it * 128 + r)) * 128 + kc * 64 + k8 * 8;
            cp16(sb + AH + doff, d_th + ao);
            cp16(sb + AL + doff, d_tl + ao);
            cp16(sb + BH + doff, d_fh + bo);
            cp16(sb + BL + doff, d_fl + bo);
        }
        CP_COMMIT(); CP_WAIT0();
        __syncthreads();

        #pragma unroll
        for (int ks = 0; ks < 4; ks++) {
            const int k0 = ks * 16;
            uint32_t ah[2][4], al[2][4];
            #pragma unroll
            for (int ma = 0; ma < 2; ma++) {
                int row = wm * 32 + ma * 16 + (g & 1) * 8 + lr;
                int col = k0 + (g >> 1) * 8;
                uint32_t ad = sb + AH + (uint32_t)(row * SLDA + col) * 2;
                ldsm4(ah[ma], ad);
                ldsm4(al[ma], ad + STILE);
            }
            #pragma unroll
            for (int np = 0; np < 4; np++) {
                int nrow = wn * 64 + np * 16 + (g >> 1) * 8 + lr;
                int ncol = k0 + (g & 1) * 8;
                uint32_t bd = sb + BH + (uint32_t)(nrow * SLDA + ncol) * 2;
                uint32_t b[4];
                ldsm4(b, bd);            // B_hi
                mma_f16(acc[0][np*2],   ah[0], b);
                mma_f16(acc[1][np*2],   ah[1], b);
                mma_f16(acc[0][np*2+1], ah[0], b+2);
                mma_f16(acc[1][np*2+1], ah[1], b+2);
                mma_f16(acc[0][np*2],   al[0], b);
                mma_f16(acc[1][np*2],   al[1], b);
                mma_f16(acc[0][np*2+1], al[0], b+2);
                mma_f16(acc[1][np*2+1], al[1], b+2);
                ldsm4(b, bd + STILE);    // B_lo
                mma_f16(acc[0][np*2],   ah[0], b);
                mma_f16(acc[1][np*2],   ah[1], b);
                mma_f16(acc[0][np*2+1], ah[0], b+2);
                mma_f16(acc[1][np*2+1], ah[1], b+2);
            }
        }
        __syncthreads();
    }

    // ---- register-direct epilogue ----
    // column (i) layout for this thread: col(nb,e) = wn*64 + nb*8 + 2*(lane&3) + e
    // rows: wm*32 + ma*16 + (lane>>2) + eh*8
    float red[8][2];
    #pragma unroll
    for (int nb = 0; nb < 8; nb++)
        #pragma unroll
        for (int e = 0; e < 2; e++)
            red[nb][e] = fmaxf(fmaxf(acc[0][nb][e], acc[0][nb][2+e]),
                               fmaxf(acc[1][nb][e], acc[1][nb][2+e]));
    #pragma unroll
    for (int s = 4; s < 32; s <<= 1)
        #pragma unroll
        for (int nb = 0; nb < 8; nb++)
            #pragma unroll
            for (int e = 0; e < 2; e++)
                red[nb][e] = fmaxf(red[nb][e],
                                   __shfl_xor_sync(0xffffffffu, red[nb][e], s));
    if (lane < 4) {
        #pragma unroll
        for (int nb = 0; nb < 8; nb++) {
            s_wm[wm][wn*64 + nb*8 + 2*lane]     = red[nb][0];
            s_wm[wm][wn*64 + nb*8 + 2*lane + 1] = red[nb][1];
        }
    }
    __syncthreads();
    if (tid < 128) {
        float m = fmaxf(fmaxf(s_wm[0][tid], s_wm[1][tid]),
                        fmaxf(s_wm[2][tid], s_wm[3][tid]));
        s_mf[tid] = m;
        d_pm[((size_t)(n * 32 + jt)) * HW + it * 128 + tid] = m;
    }
    __syncthreads();

    // exp from registers, store E scattered, accumulate z partials
    float cm0[8], cm1[8];
    #pragma unroll
    for (int nb = 0; nb < 8; nb++) {
        cm0[nb] = s_mf[wn*64 + nb*8 + 2*(lane & 3)];
        cm1[nb] = s_mf[wn*64 + nb*8 + 2*(lane & 3) + 1];
    }
    #pragma unroll
    for (int nb = 0; nb < 8; nb++) { red[nb][0] = 0.f; red[nb][1] = 0.f; }
    #pragma unroll
    for (int ma = 0; ma < 2; ma++)
        #pragma unroll
        for (int eh = 0; eh < 2; eh++) {
            int row = wm*32 + ma*16 + (lane >> 2) + eh*8;
            unsigned short* dst = d_E + ((size_t)(n * HW + jt * 128 + row)) * HW
                                + it * 128 + wn*64 + 2*(lane & 3);
            #pragma unroll
            for (int nb = 0; nb < 8; nb++) {
                float v0 = __expf(acc[ma][nb][eh*2+0] - cm0[nb]);
                float v1 = __expf(acc[ma][nb][eh*2+1] - cm1[nb]);
                red[nb][0] += v0; red[nb][1] += v1;
                ushort2 h; h.x = f2h(v0); h.y = f2h(v1);
                *(ushort2*)(dst + nb*8) = h;
            }
        }
    #pragma unroll
    for (int s = 4; s < 32; s <<= 1)
        #pragma unroll
        for (int nb = 0; nb < 8; nb++)
            #pragma unroll
            for (int e = 0; e < 2; e++)
                red[nb][e] += __shfl_xor_sync(0xffffffffu, red[nb][e], s);
    __syncthreads();   // s_wm reuse: max-phase reads done
    if (lane < 4) {
        #pragma unroll
        for (int nb = 0; nb < 8; nb++) {
            s_wm[wm][wn*64 + nb*8 + 2*lane]     = red[nb][0];
            s_wm[wm][wn*64 + nb*8 + 2*lane + 1] = red[nb][1];
        }
    }
    __syncthreads();
    if (tid < 128) {
        float z = s_wm[0][tid] + s_wm[1][tid] + s_wm[2][tid] + s_wm[3][tid];
        d_pz[((size_t)(n * 32 + jt)) * HW + it * 128 + tid] = z;
    }
}

// ============================================================================
// K3: combine 32 partials -> d_m, d_rz
// ============================================================================
__global__ __launch_bounds__(256)
void stat_combine()
{
    int idx = blockIdx.x * 256 + threadIdx.x;
    int n = idx >> 12, i = idx & 4095;
    float m = -CUDART_INF_F;
    #pragma unroll
    for (int t = 0; t < 32; t++)
        m = fmaxf(m, d_pm[((size_t)(n * 32 + t)) * HW + i]);
    float z = 0.f;
    #pragma unroll
    for (int t = 0; t < 32; t++) {
        size_t o = ((size_t)(n * 32 + t)) * HW + i;
        z += d_pz[o] * __expf(d_pm[o] - m);
    }
    d_m[n * HW + i]  = m;
    d_rz[n * HW + i] = 1.0f / z;
}

// ============================================================================
// K4: att tile = (g*fac) @ E (fac folded into A frags), then TENSOR-CORE
// fused out-proj (R15 EXACT). grid = (jt 32, n 4), 256 threads.
// ============================================================================
#define ALDA 136
#define ATB  34816
#define FAC_OFF 0
#define GA_OFF  16384
#define EB_OFF  86016
#define AH_OFF  0
#define AL_OFF  34816
#define WH_OFF  69632
#define WL_OFF  104448
#define OB_OFF  69632
#define ATT_DYN 155648

__global__ __launch_bounds__(256, 1)
void att_gemm(const float* __restrict__ x,
              const float* __restrict__ wb,
              float* __restrict__ out)
{
    extern __shared__ char sm[];
    const int jt = blockIdx.x, n = blockIdx.y;
    const int tid = threadIdx.x, wid = tid >> 5, lane = tid & 31;
    const int wm = wid & 3, wn = wid >> 2;
    const uint32_t sb = smem_u32(sm);
    uint32_t* facs2 = (uint32_t*)sm;

    float acc[2][8][4];
    #pragma unroll
    for (int a = 0; a < 2; a++)
        #pragma unroll
        for (int b = 0; b < 8; b++)
            #pragma unroll
            for (int c = 0; c < 4; c++) acc[a][b][c] = 0.f;

    const int g = lane >> 3, lr = lane & 7;

    #pragma unroll
    for (int l = 0; l < 4; l++) {
        int i4 = (tid + l * 256) * 4;
        float4 pmv = *(const float4*)(d_pm + ((size_t)(n * 32 + jt)) * HW + i4);
        float4 mv  = *(const float4*)(d_m  + (size_t)n * HW + i4);
        float4 rzv = *(const float4*)(d_rz + (size_t)n * HW + i4);
        __half2 f01 = __floats2half2_rn(__expf(pmv.x - mv.x) * rzv.x,
                                        __expf(pmv.y - mv.y) * rzv.y);
        __half2 f23 = __floats2half2_rn(__expf(pmv.z - mv.z) * rzv.z,
                                        __expf(pmv.w - mv.w) * rzv.w);
        facs2[i4/2]     = *(uint32_t*)&f01;
        facs2[i4/2 + 1] = *(uint32_t*)&f23;
    }

    auto issue = [&](int kc, int bf) {
        if (kc < 32) {
            #pragma unroll
            for (int l = 0; l < 8; l++) {
                int u = tid + l * 256, r = u >> 4, q = u & 15;
                uint32_t doff = (uint32_t)(r * ALDA + q * 8) * 2;
                cp16(sb + GA_OFF + bf * ATB + doff,
                     d_gh + ((size_t)(n * CI + r)) * HW + kc * 128 + q * 8);
                cp16(sb + EB_OFF + bf * ATB + doff,
                     d_E + ((size_t)(n * HW + jt * 128 + r)) * HW + kc * 128 + q * 8);
            }
        }
        CP_COMMIT();
    };

    issue(0, 0);
    issue(1, 1);

    for (int kc = 0; kc < 32; kc++) {
        const int bf = kc & 1;
        CP_WAIT1();
        __syncthreads();

        const uint32_t gaB = sb + GA_OFF + bf * ATB;
        const uint32_t ebB = sb + EB_OFF + bf * ATB;
        const uint32_t* facc = facs2 + kc * 64;
        #pragma unroll
        for (int ks = 0; ks < 8; ks++) {
            const int k0 = ks * 16;
            uint32_t f0 = facc[(k0 >> 1) + (lane & 3)];
            uint32_t f1 = facc[(k0 >> 1) + 4 + (lane & 3)];
            uint32_t ah[2][4];
            #pragma unroll
            for (int ma = 0; ma < 2; ma++) {
                int row = wm * 32 + ma * 16 + (g & 1) * 8 + lr;
                int col = k0 + (g >> 1) * 8;
                ldsm4(ah[ma], gaB + (uint32_t)(row * ALDA + col) * 2);
                ah[ma][0] = hmul2u(ah[ma][0], f0);
                ah[ma][1] = hmul2u(ah[ma][1], f0);
                ah[ma][2] = hmul2u(ah[ma][2], f1);
                ah[ma][3] = hmul2u(ah[ma][3], f1);
            }
            #pragma unroll
            for (int np = 0; np < 4; np++) {
                int nrow = wn * 64 + np * 16 + (g >> 1) * 8 + lr;
                int ncol = k0 + (g & 1) * 8;
                uint32_t b[4];
                ldsm4(b, ebB + (uint32_t)(nrow * ALDA + ncol) * 2);
                mma_f16(acc[0][np*2],   ah[0], b);
                mma_f16(acc[1][np*2],   ah[1], b);
                mma_f16(acc[0][np*2+1], ah[0], b+2);
                mma_f16(acc[1][np*2+1], ah[1], b+2);
            }
        }
        __syncthreads();
        issue(kc + 2, bf);
    }
    CP_WAIT0();
    __syncthreads();

    {
        unsigned short* Ah = (unsigned short*)(sm + AH_OFF);
        unsigned short* Al = (unsigned short*)(sm + AL_OFF);
        #pragma unroll
        for (int ma = 0; ma < 2; ma++) {
            int r0 = wm * 32 + ma * 16 + (lane >> 2);
            #pragma unroll
            for (int nb = 0; nb < 8; nb++) {
                int c0 = wn * 64 + nb * 8 + 2 * (lane & 3);
                #pragma unroll
                for (int e = 0; e < 4; e++) {
                    int jj = c0 + (e & 1);
                    int cc = r0 + ((e >> 1) * 8);
                    float v = acc[ma][nb][e];
                    unsigned short h = f2h(v);
                    Ah[jj * ALDA + cc] = h;
                    Al[jj * ALDA + cc] = f2h(v - h2f(h));
                }
            }
        }
    }
    __syncthreads();

    float* bufO = (float*)(sm + OB_OFF);
    for (int ch = 0; ch < 2; ch++) {
        #pragma unroll
        for (int l = 0; l < 8; l++) {
            int u = tid + l * 256, r = u >> 4, q = u & 15;
            uint32_t doff = (uint32_t)(r * ALDA + q * 8) * 2;
            cp16(sb + WH_OFF + doff, d_wh + (size_t)(ch * 128 + r) * CI + q * 8);
            cp16(sb + WL_OFF + doff, d_wl + (size_t)(ch * 128 + r) * CI + q * 8);
        }
        CP_COMMIT(); CP_WAIT0();
        __syncthreads();

        float acc2[2][8][4];
        #pragma unroll
        for (int a = 0; a < 2; a++)
            #pragma unroll
            for (int b = 0; b < 8; b++)
                #pragma unroll
                for (int c = 0; c < 4; c++) acc2[a][b][c] = 0.f;

        #pragma unroll
        for (int ks = 0; ks < 8; ks++) {
            const int k0 = ks * 16;
            uint32_t a2h[2][4], a2l[2][4];
            #pragma unroll
            for (int ma = 0; ma < 2; ma++) {
                int row = wm * 32 + ma * 16 + (g & 1) * 8 + lr;
                int col = k0 + (g >> 1) * 8;
                uint32_t ad = sb + AH_OFF + (uint32_t)(row * ALDA + col) * 2;
                ldsm4(a2h[ma], ad);
                ldsm4(a2l[ma], ad + (AL_OFF - AH_OFF));
            }
            #pragma unroll
            for (int np = 0; np < 4; np++) {
                int nrow = wn * 64 + np * 16 + (g >> 1) * 8 + lr;
                int ncol = k0 + (g & 1) * 8;
                uint32_t b[4];
                ldsm4(b, sb + WH_OFF + (uint32_t)(nrow * ALDA + ncol) * 2);
                mma_f16(acc2[0][np*2],   a2h[0], b);
                mma_f16(acc2[1][np*2],   a2h[1], b);
                mma_f16(acc2[0][np*2+1], a2h[0], b+2);
                mma_f16(acc2[1][np*2+1], a2h[1], b+2);
                mma_f16(acc2[0][np*2],   a2l[0], b);
                mma_f16(acc2[1][np*2],   a2l[1], b);
                mma_f16(acc2[0][np*2+1], a2l[0], b+2);
                mma_f16(acc2[1][np*2+1], a2l[1], b+2);
                ldsm4(b, sb + WL_OFF + (uint32_t)(nrow * ALDA + ncol) * 2);
                mma_f16(acc2[0][np*2],   a2h[0], b);
                mma_f16(acc2[1][np*2],   a2h[1], b);
                mma_f16(acc2[0][np*2+1], a2h[0], b+2);
                mma_f16(acc2[1][np*2+1], a2h[1], b+2);
            }
        }
        __syncthreads();

        #pragma unroll
        for (int ma = 0; ma < 2; ma++) {
            int r0 = wm * 32 + ma * 16 + (lane >> 2);
            #pragma unroll
            for (int nb = 0; nb < 8; nb++) {
                int c0 = wn * 64 + nb * 8 + 2 * (lane & 3);
                bufO[c0 * 132 + r0]       = acc2[ma][nb][0];
                bufO[(c0+1) * 132 + r0]   = acc2[ma][nb][1];
                bufO[c0 * 132 + r0 + 8]   = acc2[ma][nb][2];
                bufO[(c0+1) * 132 + r0+8] = acc2[ma][nb][3];
            }
        }
        __syncthreads();

        #pragma unroll
        for (int l = 0; l < 16; l++) {
            int u = tid + l * 256, row = u >> 5, jq = u & 31;
            int co = ch * 128 + row;
            float bias = wb[co];
            size_t off = ((size_t)(n * CIN + co)) * HW + jt * 128 + jq * 4;
            float4 rv = *(float4*)(bufO + row * 132 + jq * 4);
            float4 xv = *(const float4*)(x + off);
            float4 o;
            o.x = rv.x + bias + xv.x; o.y = rv.y + bias + xv.y;
            o.z = rv.z + bias + xv.z; o.w = rv.w + bias + xv.w;
            *(float4*)(out + off) = o;
        }
        __syncthreads();
    }
}

// ============================================================================
extern "C" void kernel_launch(void* const* d_in, const int* in_sizes, int n_in,
                              void* d_out, int out_size)
{
    const float* x  = (const float*)d_in[0];
    const float* tw = (const float*)d_in[1];
    const float* tb = (const float*)d_in[2];
    const float* pw = (const float*)d_in[3];
    const float* pb = (const float*)d_in[4];
    const float* gw = (const float*)d_in[5];
    const float* gb = (const float*)d_in[6];
    const float* ww = (const float*)d_in[7];
    const float* wb = (const float*)d_in[8];
    float* out = (float*)d_out;

    cudaFuncSetAttribute(s_gemm,   cudaFuncAttributeMaxDynamicSharedMemorySize, S_DYN);
    cudaFuncSetAttribute(att_gemm, cudaFuncAttributeMaxDynamicSharedMemorySize, ATT_DYN);

    w_prep<<<32, 256>>>(ww);
    proj_kernel<<<dim3(32, 4, 3), 256>>>(x, tw, tb, pw, pb, gw, gb);
    s_gemm<<<dim3(32, 32, 4), 256, S_DYN>>>();
    stat_combine<<<64, 256>>>();
    att_gemm<<<dim3(32, 4), 256, ATT_DYN>>>(x, wb, out);
}

// round 17
// speedup vs baseline: 1.2191x; 1.2191x over previous
#include <cuda_runtime.h>
#include <cuda_fp16.h>
#include <math_constants.h>
#include <cstdint>

#define NB   4
#define CIN  256
#define CI   128
#define HW   4096

// ---------------- helpers ----------------
__device__ __forceinline__ uint32_t smem_u32(const void* p) {
    uint32_t a;
    asm("{ .reg .u64 t; cvta.to.shared.u64 t, %1; cvt.u32.u64 %0, t; }" : "=r"(a) : "l"(p));
    return a;
}
__device__ __forceinline__ void ldsm4(uint32_t* r, uint32_t addr) {
    asm volatile("ldmatrix.sync.aligned.m8n8.x4.shared.b16 {%0,%1,%2,%3}, [%4];"
        : "=r"(r[0]), "=r"(r[1]), "=r"(r[2]), "=r"(r[3]) : "r"(addr));
}
__device__ __forceinline__ void ldsm4t(uint32_t* r, uint32_t addr) {
    asm volatile("ldmatrix.sync.aligned.m8n8.x4.trans.shared.b16 {%0,%1,%2,%3}, [%4];"
        : "=r"(r[0]), "=r"(r[1]), "=r"(r[2]), "=r"(r[3]) : "r"(addr));
}
__device__ __forceinline__ void mma_f16(float* c, const uint32_t* a, const uint32_t* b) {
    asm volatile("mma.sync.aligned.m16n8k16.row.col.f32.f16.f16.f32 "
        "{%0,%1,%2,%3}, {%4,%5,%6,%7}, {%8,%9}, {%0,%1,%2,%3};"
        : "+f"(c[0]), "+f"(c[1]), "+f"(c[2]), "+f"(c[3])
        : "r"(a[0]), "r"(a[1]), "r"(a[2]), "r"(a[3]), "r"(b[0]), "r"(b[1]));
}
__device__ __forceinline__ unsigned short f2h(float v) {
    return __half_as_ushort(__float2half_rn(v));
}
__device__ __forceinline__ float h2f(unsigned short u) {
    return __half2float(__ushort_as_half(u));
}
__device__ __forceinline__ uint32_t hmul2u(uint32_t a, uint32_t b) {
    __half2 r = __hmul2(*(__half2*)&a, *(__half2*)&b);
    return *(uint32_t*)&r;
}
__device__ __forceinline__ void cp16(uint32_t dst, const void* src) {
    asm volatile("cp.async.cg.shared.global [%0], [%1], 16;" :: "r"(dst), "l"(src));
}
#define CP_COMMIT() asm volatile("cp.async.commit_group;" ::: "memory")
#define CP_WAIT1()  asm volatile("cp.async.wait_group 1;" ::: "memory")
#define CP_WAIT0()  asm volatile("cp.async.wait_group 0;" ::: "memory")

// ---------------- scratch ----------------
__device__ __align__(16) unsigned short d_th[NB * HW * CI];  // theta^T hi [n][p][c]
__device__ __align__(16) unsigned short d_tl[NB * HW * CI];
__device__ __align__(16) unsigned short d_fh[NB * HW * CI];  // phi^T hi
__device__ __align__(16) unsigned short d_fl[NB * HW * CI];
__device__ __align__(16) unsigned short d_gh[NB * CI * HW];  // g hi [n][c][p]
__device__ __align__(16) unsigned short d_E [(size_t)NB * HW * HW]; // exp(S^T-pm) fp16 [n][j][i]
__device__ __align__(16) unsigned short d_wh[CIN * CI];      // w_w hi [co][c]
__device__ __align__(16) unsigned short d_wl[CIN * CI];      // w_w lo
__device__ float d_pm [NB * 32 * HW];
__device__ float d_pz [NB * 32 * HW];
__device__ float d_m  [NB * HW];
__device__ float d_rz [NB * HW];

// ============================================================================
// K0: w_w -> fp16 hi/lo
// ============================================================================
__global__ __launch_bounds__(256)
void w_prep(const float* __restrict__ ww)
{
    int i = (blockIdx.x * 256 + threadIdx.x) * 4;
    float4 v = *(const float4*)(ww + i);
    ushort4 h, l;
    h.x = f2h(v.x); h.y = f2h(v.y); h.z = f2h(v.z); h.w = f2h(v.w);
    l.x = f2h(v.x - h2f(h.x)); l.y = f2h(v.y - h2f(h.y));
    l.z = f2h(v.z - h2f(h.z)); l.w = f2h(v.w - h2f(h.w));
    *(ushort4*)(d_wh + i) = h;
    *(ushort4*)(d_wl + i) = l;
}

// ============================================================================
// K1: projections via mma.sync split-fp16 (3-pass).
// Computes O^T[p][k] = x^T[p][c] @ W[k][c]: A = x (trans ldsm from [c][p]),
// B = W (direct K-major). grid = (pt 32, n 4, pr 3), 256 thr, 2 blocks/SM.
// ============================================================================
#define PW_LDA 72
#define PX_LDA 136
#define PWH 0
#define PWL 18432
#define PXH 36864
#define PXL 54272
#define P_DYN 71680

__global__ __launch_bounds__(256, 2)
void proj_mma(const float* __restrict__ x,
              const float* __restrict__ tw, const float* __restrict__ tb,
              const float* __restrict__ pw, const float* __restrict__ pb,
              const float* __restrict__ gw, const float* __restrict__ gb)
{
    extern __shared__ char sm[];
    const int pt = blockIdx.x, n = blockIdx.y, pr = blockIdx.z;
    const float *W, *B;
    if (pr == 0)      { W = tw; B = tb; }
    else if (pr == 1) { W = pw; B = pb; }
    else              { W = gw; B = gb; }

    const int tid = threadIdx.x, wid = tid >> 5, lane = tid & 31;
    const int wm = wid & 3, wn = wid >> 2;      // p subtile 32, k subtile 64
    const uint32_t sb = smem_u32(sm);
    const int g = lane >> 3, lr = lane & 7;

    float acc[2][8][4];
    #pragma unroll
    for (int a = 0; a < 2; a++)
        #pragma unroll
        for (int b = 0; b < 8; b++)
            #pragma unroll
            for (int c = 0; c < 4; c++) acc[a][b][c] = 0.f;

    for (int kc = 0; kc < 4; kc++) {
        // stage W chunk: 128 k x 64 c, split hi/lo
        #pragma unroll
        for (int l = 0; l < 8; l++) {
            int u = tid + l * 256, k = u >> 4, cq = u & 15;
            float4 v = *(const float4*)(W + k * CIN + kc * 64 + cq * 4);
            ushort4 h, lo;
            h.x = f2h(v.x); h.y = f2h(v.y); h.z = f2h(v.z); h.w = f2h(v.w);
            lo.x = f2h(v.x - h2f(h.x)); lo.y = f2h(v.y - h2f(h.y));
            lo.z = f2h(v.z - h2f(h.z)); lo.w = f2h(v.w - h2f(h.w));
            *(ushort4*)(sm + PWH + (uint32_t)(k * PW_LDA + cq * 4) * 2) = h;
            *(ushort4*)(sm + PWL + (uint32_t)(k * PW_LDA + cq * 4) * 2) = lo;
        }
        // stage x chunk: 64 c x 128 p, split hi/lo (natural [c][p] layout)
        #pragma unroll
        for (int l = 0; l < 8; l++) {
            int u = tid + l * 256, c = u >> 5, p4 = u & 31;
            float4 v = *(const float4*)(x + ((size_t)(n * CIN + kc * 64 + c)) * HW
                                          + pt * 128 + p4 * 4);
            ushort4 h, lo;
            h.x = f2h(v.x); h.y = f2h(v.y); h.z = f2h(v.z); h.w = f2h(v.w);
            lo.x = f2h(v.x - h2f(h.x)); lo.y = f2h(v.y - h2f(h.y));
            lo.z = f2h(v.z - h2f(h.z)); lo.w = f2h(v.w - h2f(h.w));
            *(ushort4*)(sm + PXH + (uint32_t)(c * PX_LDA + p4 * 4) * 2) = h;
            *(ushort4*)(sm + PXL + (uint32_t)(c * PX_LDA + p4 * 4) * 2) = lo;
        }
        __syncthreads();

        #pragma unroll
        for (int ks = 0; ks < 4; ks++) {
            const int k0 = ks * 16;   // c offset within chunk
            uint32_t axh[2][4], axl[2][4];
            #pragma unroll
            for (int ma = 0; ma < 2; ma++) {
                int m0 = wm * 32 + ma * 16;
                // trans A: addr row = c (k-dim), col = p (m-dim)
                uint32_t ad = sb + PXH
                    + (uint32_t)((k0 + (g >> 1) * 8 + lr) * PX_LDA
                                 + m0 + (g & 1) * 8) * 2;
                ldsm4t(axh[ma], ad);
                ldsm4t(axl[ma], ad + (PXL - PXH));
            }
            #pragma unroll
            for (int np = 0; np < 4; np++) {
                int nrow = wn * 64 + np * 16 + (g >> 1) * 8 + lr;  // k_out
                int ncol = k0 + (g & 1) * 8;                       // c
                uint32_t bd = sb + PWH + (uint32_t)(nrow * PW_LDA + ncol) * 2;
                uint32_t b[4];
                ldsm4(b, bd);                  // W_hi
                mma_f16(acc[0][np*2],   axh[0], b);
                mma_f16(acc[1][np*2],   axh[1], b);
                mma_f16(acc[0][np*2+1], axh[0], b+2);
                mma_f16(acc[1][np*2+1], axh[1], b+2);
                mma_f16(acc[0][np*2],   axl[0], b);
                mma_f16(acc[1][np*2],   axl[1], b);
                mma_f16(acc[0][np*2+1], axl[0], b+2);
                mma_f16(acc[1][np*2+1], axl[1], b+2);
                ldsm4(b, bd + (PWL - PWH));    // W_lo
                mma_f16(acc[0][np*2],   axh[0], b);
                mma_f16(acc[1][np*2],   axh[1], b);
                mma_f16(acc[0][np*2+1], axh[0], b+2);
                mma_f16(acc[1][np*2+1], axh[1], b+2);
            }
        }
        __syncthreads();
    }

    // bias (indexed by k = frag column)
    #pragma unroll
    for (int nb = 0; nb < 8; nb++) {
        float b0 = B[wn*64 + nb*8 + 2*(lane & 3)];
        float b1 = B[wn*64 + nb*8 + 2*(lane & 3) + 1];
        #pragma unroll
        for (int ma = 0; ma < 2; ma++) {
            acc[ma][nb][0] += b0; acc[ma][nb][1] += b1;
            acc[ma][nb][2] += b0; acc[ma][nb][3] += b1;
        }
    }

    unsigned short* Hh = (unsigned short*)sm;            // [128][136]
    unsigned short* Hl = (unsigned short*)(sm + 34816);  // [128][136]

    if (pr < 2) {
        // D rows = p, cols = k: native [p][k] layout; split hi/lo
        #pragma unroll
        for (int ma = 0; ma < 2; ma++) {
            int r0 = wm * 32 + ma * 16 + (lane >> 2);
            #pragma unroll
            for (int nb = 0; nb < 8; nb++) {
                int c0 = wn * 64 + nb * 8 + 2 * (lane & 3);
                #pragma unroll
                for (int eh = 0; eh < 2; eh++) {
                    int r = r0 + eh * 8;
                    float v0 = acc[ma][nb][eh*2+0], v1 = acc[ma][nb][eh*2+1];
                    ushort2 h, lo;
                    h.x = f2h(v0); h.y = f2h(v1);
                    lo.x = f2h(v0 - h2f(h.x)); lo.y = f2h(v1 - h2f(h.y));
                    *(ushort2*)(Hh + r * PX_LDA + c0) = h;
                    *(ushort2*)(Hl + r * PX_LDA + c0) = lo;
                }
            }
        }
        __syncthreads();
        unsigned short* DH = (pr == 0) ? d_th : d_fh;
        unsigned short* DL = (pr == 0) ? d_tl : d_fl;
        #pragma unroll
        for (int l = 0; l < 8; l++) {
            int u = tid + l * 256, row = u >> 4, q = u & 15;
            size_t off = ((size_t)(n * HW + pt * 128 + row)) * 128 + q * 8;
            *(uint4*)(DH + off) = *(uint4*)(Hh + row * PX_LDA + q * 8);
            *(uint4*)(DL + off) = *(uint4*)(Hl + row * PX_LDA + q * 8);
        }
    } else {
        // g: need [k][p] -> transpose through smem (hi only)
        #pragma unroll
        for (int ma = 0; ma < 2; ma++) {
            int r0 = wm * 32 + ma * 16 + (lane >> 2);
            #pragma unroll
            for (int nb = 0; nb < 8; nb++) {
                int c0 = wn * 64 + nb * 8 + 2 * (lane & 3);
                Hh[c0 * PX_LDA + r0]         = f2h(acc[ma][nb][0]);
                Hh[(c0+1) * PX_LDA + r0]     = f2h(acc[ma][nb][1]);
                Hh[c0 * PX_LDA + r0 + 8]     = f2h(acc[ma][nb][2]);
                Hh[(c0+1) * PX_LDA + r0 + 8] = f2h(acc[ma][nb][3]);
            }
        }
        __syncthreads();
        #pragma unroll
        for (int l = 0; l < 8; l++) {
            int u = tid + l * 256, k = u >> 4, q = u & 15;
            *(uint4*)(d_gh + ((size_t)(n * CI + k)) * HW + pt * 128 + q * 8)
                = *(uint4*)(Hh + k * PX_LDA + q * 8);
        }
    }
}

// ============================================================================
// K2: S^T[j][i] via mma.sync fp16 split — R15 EXACT
// grid = (it 32, jt 32, n 4)
// ============================================================================
#define SLDA 72
#define STILE 18432
#define S_DYN (4 * STILE)

__global__ __launch_bounds__(256, 2)
void s_gemm()
{
    extern __shared__ char sm[];
    const int it = blockIdx.x, jt = blockIdx.y, n = blockIdx.z;
    const int tid = threadIdx.x, wid = tid >> 5, lane = tid & 31;
    const int wm = wid & 3, wn = wid >> 2;
    const uint32_t sb = smem_u32(sm);
    const uint32_t AH = 0, AL = STILE, BH = 2*STILE, BL = 3*STILE;

    __shared__ float s_pm2[2][128], s_mf[128], s_red[16][128];

    float acc[2][8][4];
    #pragma unroll
    for (int a = 0; a < 2; a++)
        #pragma unroll
        for (int b = 0; b < 8; b++)
            #pragma unroll
            for (int c = 0; c < 4; c++) acc[a][b][c] = 0.f;

    const int g = lane >> 3, lr = lane & 7;

    for (int kc = 0; kc < 2; kc++) {
        #pragma unroll
        for (int l = 0; l < 4; l++) {
            int u = tid + l * 256, r = u >> 3, k8 = u & 7;
            uint32_t doff = (uint32_t)(r * SLDA + k8 * 8) * 2;
            size_t ao = ((size_t)(n * HW + jt * 128 + r)) * 128 + kc * 64 + k8 * 8;
            size_t bo = ((size_t)(n * HW + it * 128 + r)) * 128 + kc * 64 + k8 * 8;
            cp16(sb + AH + doff, d_th + ao);
            cp16(sb + AL + doff, d_tl + ao);
            cp16(sb + BH + doff, d_fh + bo);
            cp16(sb + BL + doff, d_fl + bo);
        }
        CP_COMMIT(); CP_WAIT0();
        __syncthreads();

        #pragma unroll
        for (int ks = 0; ks < 4; ks++) {
            const int k0 = ks * 16;
            uint32_t ah[2][4], al[2][4];
            #pragma unroll
            for (int ma = 0; ma < 2; ma++) {
                int row = wm * 32 + ma * 16 + (g & 1) * 8 + lr;
                int col = k0 + (g >> 1) * 8;
                uint32_t ad = sb + AH + (uint32_t)(row * SLDA + col) * 2;
                ldsm4(ah[ma], ad);
                ldsm4(al[ma], ad + STILE);
            }
            #pragma unroll
            for (int np = 0; np < 4; np++) {
                int nrow = wn * 64 + np * 16 + (g >> 1) * 8 + lr;
                int ncol = k0 + (g & 1) * 8;
                uint32_t bd = sb + BH + (uint32_t)(nrow * SLDA + ncol) * 2;
                uint32_t b[4];
                ldsm4(b, bd);            // B_hi
                mma_f16(acc[0][np*2],   ah[0], b);
                mma_f16(acc[1][np*2],   ah[1], b);
                mma_f16(acc[0][np*2+1], ah[0], b+2);
                mma_f16(acc[1][np*2+1], ah[1], b+2);
                mma_f16(acc[0][np*2],   al[0], b);
                mma_f16(acc[1][np*2],   al[1], b);
                mma_f16(acc[0][np*2+1], al[0], b+2);
                mma_f16(acc[1][np*2+1], al[1], b+2);
                ldsm4(b, bd + STILE);    // B_lo
                mma_f16(acc[0][np*2],   ah[0], b);
                mma_f16(acc[1][np*2],   ah[1], b);
                mma_f16(acc[0][np*2+1], ah[0], b+2);
                mma_f16(acc[1][np*2+1], ah[1], b+2);
            }
        }
        __syncthreads();
    }

    float* buf = (float*)sm;
    #pragma unroll
    for (int ma = 0; ma < 2; ma++) {
        int r0 = wm * 32 + ma * 16 + (lane >> 2);
        #pragma unroll
        for (int nb = 0; nb < 8; nb++) {
            int c0 = wn * 64 + nb * 8 + 2 * (lane & 3);
            buf[r0 * 132 + c0]       = acc[ma][nb][0];
            buf[r0 * 132 + c0 + 1]   = acc[ma][nb][1];
            buf[(r0+8) * 132 + c0]   = acc[ma][nb][2];
            buf[(r0+8) * 132 + c0+1] = acc[ma][nb][3];
        }
    }
    __syncthreads();

    {
        int i = tid & 127, hf = tid >> 7;
        float mx = -CUDART_INF_F;
        #pragma unroll 4
        for (int r = 0; r < 64; r++) mx = fmaxf(mx, buf[(hf * 64 + r) * 132 + i]);
        s_pm2[hf][i] = mx;
    }
    __syncthreads();
    if (tid < 128) {
        float m = fmaxf(s_pm2[0][tid], s_pm2[1][tid]);
        s_mf[tid] = m;
        d_pm[((size_t)(n * 32 + jt)) * HW + it * 128 + tid] = m;
    }
    __syncthreads();

    {
        float zp[8];
        #pragma unroll
        for (int e = 0; e < 8; e++) zp[e] = 0.f;
        const int q = tid & 15;
        #pragma unroll
        for (int l = 0; l < 8; l++) {
            int r = (tid >> 4) + l * 16;
            const float* row = buf + r * 132 + q * 8;
            float v[8];
            #pragma unroll
            for (int e = 0; e < 8; e++) {
                v[e] = __expf(row[e] - s_mf[q*8+e]);
                zp[e] += v[e];
            }
            ushort4 h0, h1;
            h0.x = f2h(v[0]); h0.y = f2h(v[1]); h0.z = f2h(v[2]); h0.w = f2h(v[3]);
            h1.x = f2h(v[4]); h1.y = f2h(v[5]); h1.z = f2h(v[6]); h1.w = f2h(v[7]);
            unsigned short* dst = d_E + ((size_t)(n * HW + jt * 128 + r)) * HW + it * 128 + q * 8;
            *(ushort4*)(dst)     = h0;
            *(ushort4*)(dst + 4) = h1;
        }
        #pragma unroll
        for (int e = 0; e < 8; e++) s_red[tid >> 4][q * 8 + e] = zp[e];
    }
    __syncthreads();
    if (tid < 128) {
        float z = 0.f;
        #pragma unroll
        for (int t = 0; t < 16; t++) z += s_red[t][tid];
        d_pz[((size_t)(n * 32 + jt)) * HW + it * 128 + tid] = z;
    }
}

// ============================================================================
// K3: combine 32 partials -> d_m, d_rz
// ============================================================================
__global__ __launch_bounds__(256)
void stat_combine()
{
    int idx = blockIdx.x * 256 + threadIdx.x;
    int n = idx >> 12, i = idx & 4095;
    float m = -CUDART_INF_F;
    #pragma unroll
    for (int t = 0; t < 32; t++)
        m = fmaxf(m, d_pm[((size_t)(n * 32 + t)) * HW + i]);
    float z = 0.f;
    #pragma unroll
    for (int t = 0; t < 32; t++) {
        size_t o = ((size_t)(n * 32 + t)) * HW + i;
        z += d_pz[o] * __expf(d_pm[o] - m);
    }
    d_m[n * HW + i]  = m;
    d_rz[n * HW + i] = 1.0f / z;
}

// ============================================================================
// K4: att tile = (g*fac) @ E + tensor-core fused out-proj — R15 EXACT
// grid = (jt 32, n 4), 256 threads.
// ============================================================================
#define ALDA 136
#define ATB  34816
#define FAC_OFF 0
#define GA_OFF  16384
#define EB_OFF  86016
#define AH_OFF  0
#define AL_OFF  34816
#define WH_OFF  69632
#define WL_OFF  104448
#define OB_OFF  69632
#define ATT_DYN 155648

__global__ __launch_bounds__(256, 1)
void att_gemm(const float* __restrict__ x,
              const float* __restrict__ wb,
              float* __restrict__ out)
{
    extern __shared__ char sm[];
    const int jt = blockIdx.x, n = blockIdx.y;
    const int tid = threadIdx.x, wid = tid >> 5, lane = tid & 31;
    const int wm = wid & 3, wn = wid >> 2;
    const uint32_t sb = smem_u32(sm);
    uint32_t* facs2 = (uint32_t*)sm;

    float acc[2][8][4];
    #pragma unroll
    for (int a = 0; a < 2; a++)
        #pragma unroll
        for (int b = 0; b < 8; b++)
            #pragma unroll
            for (int c = 0; c < 4; c++) acc[a][b][c] = 0.f;

    const int g = lane >> 3, lr = lane & 7;

    #pragma unroll
    for (int l = 0; l < 4; l++) {
        int i4 = (tid + l * 256) * 4;
        float4 pmv = *(const float4*)(d_pm + ((size_t)(n * 32 + jt)) * HW + i4);
        float4 mv  = *(const float4*)(d_m  + (size_t)n * HW + i4);
        float4 rzv = *(const float4*)(d_rz + (size_t)n * HW + i4);
        __half2 f01 = __floats2half2_rn(__expf(pmv.x - mv.x) * rzv.x,
                                        __expf(pmv.y - mv.y) * rzv.y);
        __half2 f23 = __floats2half2_rn(__expf(pmv.z - mv.z) * rzv.z,
                                        __expf(pmv.w - mv.w) * rzv.w);
        facs2[i4/2]     = *(uint32_t*)&f01;
        facs2[i4/2 + 1] = *(uint32_t*)&f23;
    }

    auto issue = [&](int kc, int bf) {
        if (kc < 32) {
            #pragma unroll
            for (int l = 0; l < 8; l++) {
                int u = tid + l * 256, r = u >> 4, q = u & 15;
                uint32_t doff = (uint32_t)(r * ALDA + q * 8) * 2;
                cp16(sb + GA_OFF + bf * ATB + doff,
                     d_gh + ((size_t)(n * CI + r)) * HW + kc * 128 + q * 8);
                cp16(sb + EB_OFF + bf * ATB + doff,
                     d_E + ((size_t)(n * HW + jt * 128 + r)) * HW + kc * 128 + q * 8);
            }
        }
        CP_COMMIT();
    };

    issue(0, 0);
    issue(1, 1);

    for (int kc = 0; kc < 32; kc++) {
        const int bf = kc & 1;
        CP_WAIT1();
        __syncthreads();

        const uint32_t gaB = sb + GA_OFF + bf * ATB;
        const uint32_t ebB = sb + EB_OFF + bf * ATB;
        const uint32_t* facc = facs2 + kc * 64;
        #pragma unroll
        for (int ks = 0; ks < 8; ks++) {
            const int k0 = ks * 16;
            uint32_t f0 = facc[(k0 >> 1) + (lane & 3)];
            uint32_t f1 = facc[(k0 >> 1) + 4 + (lane & 3)];
            uint32_t ah[2][4];
            #pragma unroll
            for (int ma = 0; ma < 2; ma++) {
                int row = wm * 32 + ma * 16 + (g & 1) * 8 + lr;
                int col = k0 + (g >> 1) * 8;
                ldsm4(ah[ma], gaB + (uint32_t)(row * ALDA + col) * 2);
                ah[ma][0] = hmul2u(ah[ma][0], f0);
                ah[ma][1] = hmul2u(ah[ma][1], f0);
                ah[ma][2] = hmul2u(ah[ma][2], f1);
                ah[ma][3] = hmul2u(ah[ma][3], f1);
            }
            #pragma unroll
            for (int np = 0; np < 4; np++) {
                int nrow = wn * 64 + np * 16 + (g >> 1) * 8 + lr;
                int ncol = k0 + (g & 1) * 8;
                uint32_t b[4];
                ldsm4(b, ebB + (uint32_t)(nrow * ALDA + ncol) * 2);
                mma_f16(acc[0][np*2],   ah[0], b);
                mma_f16(acc[1][np*2],   ah[1], b);
                mma_f16(acc[0][np*2+1], ah[0], b+2);
                mma_f16(acc[1][np*2+1], ah[1], b+2);
            }
        }
        __syncthreads();
        issue(kc + 2, bf);
    }
    CP_WAIT0();
    __syncthreads();

    {
        unsigned short* Ah = (unsigned short*)(sm + AH_OFF);
        unsigned short* Al = (unsigned short*)(sm + AL_OFF);
        #pragma unroll
        for (int ma = 0; ma < 2; ma++) {
            int r0 = wm * 32 + ma * 16 + (lane >> 2);
            #pragma unroll
            for (int nb = 0; nb < 8; nb++) {
                int c0 = wn * 64 + nb * 8 + 2 * (lane & 3);
                #pragma unroll
                for (int e = 0; e < 4; e++) {
                    int jj = c0 + (e & 1);
                    int cc = r0 + ((e >> 1) * 8);
                    float v = acc[ma][nb][e];
                    unsigned short h = f2h(v);
                    Ah[jj * ALDA + cc] = h;
                    Al[jj * ALDA + cc] = f2h(v - h2f(h));
                }
            }
        }
    }
    __syncthreads();

    float* bufO = (float*)(sm + OB_OFF);
    for (int ch = 0; ch < 2; ch++) {
        #pragma unroll
        for (int l = 0; l < 8; l++) {
            int u = tid + l * 256, r = u >> 4, q = u & 15;
            uint32_t doff = (uint32_t)(r * ALDA + q * 8) * 2;
            cp16(sb + WH_OFF + doff, d_wh + (size_t)(ch * 128 + r) * CI + q * 8);
            cp16(sb + WL_OFF + doff, d_wl + (size_t)(ch * 128 + r) * CI + q * 8);
        }
        CP_COMMIT(); CP_WAIT0();
        __syncthreads();

        float acc2[2][8][4];
        #pragma unroll
        for (int a = 0; a < 2; a++)
            #pragma unroll
            for (int b = 0; b < 8; b++)
                #pragma unroll
                for (int c = 0; c < 4; c++) acc2[a][b][c] = 0.f;

        #pragma unroll
        for (int ks = 0; ks < 8; ks++) {
            const int k0 = ks * 16;
            uint32_t a2h[2][4], a2l[2][4];
            #pragma unroll
            for (int ma = 0; ma < 2; ma++) {
                int row = wm * 32 + ma * 16 + (g & 1) * 8 + lr;
                int col = k0 + (g >> 1) * 8;
                uint32_t ad = sb + AH_OFF + (uint32_t)(row * ALDA + col) * 2;
                ldsm4(a2h[ma], ad);
                ldsm4(a2l[ma], ad + (AL_OFF - AH_OFF));
            }
            #pragma unroll
            for (int np = 0; np < 4; np++) {
                int nrow = wn * 64 + np * 16 + (g >> 1) * 8 + lr;
                int ncol = k0 + (g & 1) * 8;
                uint32_t b[4];
                ldsm4(b, sb + WH_OFF + (uint32_t)(nrow * ALDA + ncol) * 2);
                mma_f16(acc2[0][np*2],   a2h[0], b);
                mma_f16(acc2[1][np*2],   a2h[1], b);
                mma_f16(acc2[0][np*2+1], a2h[0], b+2);
                mma_f16(acc2[1][np*2+1], a2h[1], b+2);
                mma_f16(acc2[0][np*2],   a2l[0], b);
                mma_f16(acc2[1][np*2],   a2l[1], b);
                mma_f16(acc2[0][np*2+1], a2l[0], b+2);
                mma_f16(acc2[1][np*2+1], a2l[1], b+2);
                ldsm4(b, sb + WL_OFF + (uint32_t)(nrow * ALDA + ncol) * 2);
                mma_f16(acc2[0][np*2],   a2h[0], b);
                mma_f16(acc2[1][np*2],   a2h[1], b);
                mma_f16(acc2[0][np*2+1], a2h[0], b+2);
                mma_f16(acc2[1][np*2+1], a2h[1], b+2);
            }
        }
        __syncthreads();

        #pragma unroll
        for (int ma = 0; ma < 2; ma++) {
            int r0 = wm * 32 + ma * 16 + (lane >> 2);
            #pragma unroll
            for (int nb = 0; nb < 8; nb++) {
                int c0 = wn * 64 + nb * 8 + 2 * (lane & 3);
                bufO[c0 * 132 + r0]       = acc2[ma][nb][0];
                bufO[(c0+1) * 132 + r0]   = acc2[ma][nb][1];
                bufO[c0 * 132 + r0 + 8]   = acc2[ma][nb][2];
                bufO[(c0+1) * 132 + r0+8] = acc2[ma][nb][3];
            }
        }
        __syncthreads();

        #pragma unroll
        for (int l = 0; l < 16; l++) {
            int u = tid + l * 256, row = u >> 5, jq = u & 31;
            int co = ch * 128 + row;
            float bias = wb[co];
            size_t off = ((size_t)(n * CIN + co)) * HW + jt * 128 + jq * 4;
            float4 rv = *(float4*)(bufO + row * 132 + jq * 4);
            float4 xv = *(const float4*)(x + off);
            float4 o;
            o.x = rv.x + bias + xv.x; o.y = rv.y + bias + xv.y;
            o.z = rv.z + bias + xv.z; o.w = rv.w + bias + xv.w;
            *(float4*)(out + off) = o;
        }
        __syncthreads();
    }
}

// ============================================================================
extern "C" void kernel_launch(void* const* d_in, const int* in_sizes, int n_in,
                              void* d_out, int out_size)
{
    const float* x  = (const float*)d_in[0];
    const float* tw = (const float*)d_in[1];
    const float* tb = (const float*)d_in[2];
    const float* pw = (const float*)d_in[3];
    const float* pb = (const float*)d_in[4];
    const float* gw = (const float*)d_in[5];
    const float* gb = (const float*)d_in[6];
    const float* ww = (const float*)d_in[7];
    const float* wb = (const float*)d_in[8];
    float* out = (float*)d_out;

    cudaFuncSetAttribute(proj_mma, cudaFuncAttributeMaxDynamicSharedMemorySize, P_DYN);
    cudaFuncSetAttribute(s_gemm,   cudaFuncAttributeMaxDynamicSharedMemorySize, S_DYN);
    cudaFuncSetAttribute(att_gemm, cudaFuncAttributeMaxDynamicSharedMemorySize, ATT_DYN);

    w_prep<<<32, 256>>>(ww);
    proj_mma<<<dim3(32, 4, 3), 256, P_DYN>>>(x, tw, tb, pw, pb, gw, gb);
    s_gemm<<<dim3(32, 32, 4), 256, S_DYN>>>();
    stat_combine<<<64, 256>>>();
    att_gemm<<<dim3(32, 4), 256, ATT_DYN>>>(x, wb, out);
}